// round 14
// baseline (speedup 1.0000x reference)
#include <cuda_runtime.h>
#include <cuda_fp16.h>
#include <math.h>
#include <stdint.h>

// Problem dims (fixed)
#define BSZ   4096
#define KDIM  1024
#define N4    4096   // 4*H
#define HDIM  1024

// ---------------------------------------------------------------------------
// Device scratch (static, no dynamic allocation)
// ---------------------------------------------------------------------------
__device__ __half g_gi[(size_t)BSZ * N4];   // input  @ w_i2h + b_i2h (fp16)
__device__ __half g_gh[(size_t)BSZ * N4];   // h_prev @ w_h2h + b_h2h (fp16)

// per-row partial LN statistics from GEMM epilogue: [gemm][nCTA][row]=(sum,sumsq)
__device__ float2 g_part[2][16][BSZ];

// fp16 operands: A [BSZ, KDIM], W transposed [N4, KDIM]
__device__ __half g_a2[2][(size_t)BSZ * KDIM];
__device__ __half g_w2[2][(size_t)N4 * KDIM];

// ---------------------------------------------------------------------------
// Base-PTX helpers (legal on compute_103 virtual arch)
// ---------------------------------------------------------------------------
__device__ __forceinline__ uint32_t smem_u32(const void* p) {
    uint32_t a;
    asm("{ .reg .u64 t; cvta.to.shared.u64 t, %1; cvt.u32.u64 %0, t; }" : "=r"(a) : "l"(p));
    return a;
}
__device__ __forceinline__ void cp_async16(uint32_t s, const void* g) {
    asm volatile("cp.async.cg.shared.global [%0], [%1], 16;" :: "r"(s), "l"(g));
}
#define CP_COMMIT() asm volatile("cp.async.commit_group;" ::: "memory")
#define CP_WAIT(n)  asm volatile("cp.async.wait_group %0;" :: "n"(n) : "memory")

__device__ __forceinline__ void ldsm4(uint32_t& r0, uint32_t& r1, uint32_t& r2, uint32_t& r3,
                                      uint32_t addr) {
    asm volatile("ldmatrix.sync.aligned.m8n8.x4.shared.b16 {%0,%1,%2,%3}, [%4];"
                 : "=r"(r0), "=r"(r1), "=r"(r2), "=r"(r3) : "r"(addr));
}
__device__ __forceinline__ void mma_f16(float* c, const uint32_t* a, const uint32_t* b) {
    asm volatile(
        "mma.sync.aligned.m16n8k16.row.col.f32.f16.f16.f32 "
        "{%0,%1,%2,%3}, {%4,%5,%6,%7}, {%8,%9}, {%0,%1,%2,%3};"
        : "+f"(c[0]), "+f"(c[1]), "+f"(c[2]), "+f"(c[3])
        : "r"(a[0]), "r"(a[1]), "r"(a[2]), "r"(a[3]), "r"(b[0]), "r"(b[1]));
}

// fast transcendental approximations (single MUFU op each)
__device__ __forceinline__ float fast_tanh(float x) {
    float y;
    asm("tanh.approx.f32 %0, %1;" : "=f"(y) : "f"(x));
    return y;
}
__device__ __forceinline__ float fast_sigmoid(float x) {
    float e;
    asm("ex2.approx.f32 %0, %1;" : "=f"(e) : "f"(-1.4426950408889634f * x));
    float r;
    asm("rcp.approx.f32 %0, %1;" : "=f"(r) : "f"(1.0f + e));
    return r;
}
__device__ __forceinline__ float fast_sqrt(float x) {
    float y;
    asm("sqrt.approx.f32 %0, %1;" : "=f"(y) : "f"(x));
    return y;
}
__device__ __forceinline__ float fast_rcp(float x) {
    float y;
    asm("rcp.approx.f32 %0, %1;" : "=f"(y) : "f"(x));
    return y;
}

// ---------------------------------------------------------------------------
// Conversion kernels
// ---------------------------------------------------------------------------
__global__ void __launch_bounds__(256) cast_act_kernel(
    const float* __restrict__ src0, const float* __restrict__ src1)
{
    const int plane = blockIdx.z;
    const float* __restrict__ src = plane ? src1 : src0;
    __half* __restrict__ dst = g_a2[plane];

    const size_t idx = ((size_t)blockIdx.x * 256 + threadIdx.x) * 4;
    float4 v = *(const float4*)(src + idx);
    union { __half2 h2v[2]; uint2 u; } p;
    p.h2v[0] = __floats2half2_rn(v.x, v.y);
    p.h2v[1] = __floats2half2_rn(v.z, v.w);
    *(uint2*)(dst + idx) = p.u;
}

// Weights: W [KDIM, N4] fp32 -> W2 [N4, KDIM] fp16 (transpose), vectorized.
__global__ void __launch_bounds__(128) cast_wt_kernel(
    const float* __restrict__ w0, const float* __restrict__ w1)
{
    const int plane = blockIdx.z;
    const float* __restrict__ W = plane ? w1 : w0;
    __half* __restrict__ D = g_w2[plane];

    __shared__ float tileT[32][33];      // [n][k]
    const int tid = threadIdx.x;
    const int n0 = blockIdx.x * 32;      // N tile
    const int k0 = blockIdx.y * 32;      // K tile

    #pragma unroll
    for (int it = 0; it < 2; it++) {
        const int id = tid + it * 128;
        const int k  = id >> 3;              // 0..31
        const int n4 = (id & 7) * 4;         // 0,4,..28
        const float4 v = *(const float4*)(W + (size_t)(k0 + k) * N4 + n0 + n4);
        tileT[n4 + 0][k] = v.x;
        tileT[n4 + 1][k] = v.y;
        tileT[n4 + 2][k] = v.z;
        tileT[n4 + 3][k] = v.w;
    }
    __syncthreads();

    const int n  = tid >> 2;                 // 0..31
    const int kc = (tid & 3) * 8;            // 0,8,16,24
    union { __half2 h[4]; uint4 u; } o;
    #pragma unroll
    for (int i = 0; i < 4; i++)
        o.h[i] = __floats2half2_rn(tileT[n][kc + i * 2], tileT[n][kc + i * 2 + 1]);
    *(uint4*)(D + (size_t)(n0 + n) * KDIM + k0 + kc) = o.u;
}

// ---------------------------------------------------------------------------
// fp16 mma.sync GEMM + fused per-row partial LN statistics.
// CTA tile 128x256, BK=32, 512 threads (16 warps, 4x4), warp tile 32x64,
// 4-stage cp.async pipeline. Output fp16; row (sum,sumsq) partials -> g_part.
// ---------------------------------------------------------------------------
#define BM 128
#define BN 256
#define BK 32
#define STAGES 4
#define A_ST ((BM) * (BK) * 2)                  // 8192 B
#define B_ST ((BN) * (BK) * 2)                  // 16384 B
#define STAGE_BYTES (A_ST + B_ST)               // 24576 B
#define GEMM_SMEM (STAGES * STAGE_BYTES)        // 98304 B
#define ITERS (KDIM / BK)                       // 32

__device__ __forceinline__ uint32_t sw_off(int r, int chunk) {
    return (uint32_t)(r * 64 + ((chunk ^ ((r >> 1) & 3)) << 4));
}

__device__ __forceinline__ void load_stage(
    uint32_t sA, uint32_t sB,
    const __half* __restrict__ Ag, const __half* __restrict__ Wg,
    int m0, int n0, int kt, int tid)
{
    const int kbase = kt * BK;
    {
        const int r = tid >> 2, kc = tid & 3;
        cp_async16(sA + sw_off(r, kc), Ag + (size_t)(m0 + r) * KDIM + kbase + kc * 8);
    }
    #pragma unroll
    for (int i = 0; i < 2; i++) {
        const int id = tid + i * 512;
        const int r = id >> 2, kc = id & 3;
        cp_async16(sB + sw_off(r, kc), Wg + (size_t)(n0 + r) * KDIM + kbase + kc * 8);
    }
}

__global__ void __launch_bounds__(512, 1) gemm_mma_kernel(
    const float* __restrict__ bias0, const float* __restrict__ bias1)
{
    extern __shared__ char smem[];
    const uint32_t sbase = smem_u32(smem);
    const int tid  = threadIdx.x;
    const int lane = tid & 31;
    const int wid  = tid >> 5;
    const int wm   = wid >> 2;     // 0..3
    const int wn   = wid & 3;      // 0..3

    const int gemm = blockIdx.z;
    const int m0 = blockIdx.y * BM;
    const int n0 = blockIdx.x * BN;

    const __half* __restrict__ Ag = g_a2[gemm];
    const __half* __restrict__ Wg = g_w2[gemm];
    __half* __restrict__ C = gemm ? g_gh : g_gi;
    const float* __restrict__ bias = gemm ? bias1 : bias0;

    float acc[2][8][4];
    #pragma unroll
    for (int i = 0; i < 2; i++)
        #pragma unroll
        for (int j = 0; j < 8; j++)
            #pragma unroll
            for (int r = 0; r < 4; r++)
                acc[i][j][r] = 0.0f;

    const int row_a  = lane & 15;
    const int ksel_a = lane >> 4;
    const int row_b  = ((lane >> 4) << 3) | (lane & 7);
    const int ksel_b = (lane >> 3) & 1;

    load_stage(sbase,                   sbase + A_ST,                   Ag, Wg, m0, n0, 0, tid);
    CP_COMMIT();
    load_stage(sbase + STAGE_BYTES,     sbase + STAGE_BYTES + A_ST,     Ag, Wg, m0, n0, 1, tid);
    CP_COMMIT();
    load_stage(sbase + 2 * STAGE_BYTES, sbase + 2 * STAGE_BYTES + A_ST, Ag, Wg, m0, n0, 2, tid);
    CP_COMMIT();

    #pragma unroll 1
    for (int kt = 0; kt < ITERS; kt++) {
        CP_WAIT(2);
        __syncthreads();
        const int s = kt & 3;
        const uint32_t sA = sbase + s * STAGE_BYTES;
        const uint32_t sB = sA + A_ST;

        #pragma unroll
        for (int ks = 0; ks < 2; ks++) {
            uint32_t a[2][4], b[4][4];
            #pragma unroll
            for (int mt = 0; mt < 2; mt++) {
                const int r = wm * 32 + mt * 16 + row_a;
                ldsm4(a[mt][0], a[mt][1], a[mt][2], a[mt][3],
                      sA + sw_off(r, ks * 2 + ksel_a));
            }
            #pragma unroll
            for (int bt = 0; bt < 4; bt++) {
                const int n = wn * 64 + bt * 16 + row_b;
                ldsm4(b[bt][0], b[bt][1], b[bt][2], b[bt][3],
                      sB + sw_off(n, ks * 2 + ksel_b));
            }
            #pragma unroll
            for (int mt = 0; mt < 2; mt++)
                #pragma unroll
                for (int bt = 0; bt < 4; bt++) {
                    mma_f16(acc[mt][bt * 2],     a[mt], &b[bt][0]);
                    mma_f16(acc[mt][bt * 2 + 1], a[mt], &b[bt][2]);
                }
        }

        if (kt + 3 < ITERS) {
            const int sn = (kt + 3) & 3;
            load_stage(sbase + sn * STAGE_BYTES, sbase + sn * STAGE_BYTES + A_ST,
                       Ag, Wg, m0, n0, kt + 3, tid);
        }
        CP_COMMIT();
    }

    // all warps out of the mainloop before smem is reused for reductions
    __syncthreads();

    float2 bv[8];
    #pragma unroll
    for (int nf = 0; nf < 8; nf++) {
        const int n = n0 + wn * 64 + nf * 8 + (lane & 3) * 2;
        bv[nf] = *(const float2*)(bias + n);
    }

    // store fp16 + per-thread row sums (rows: [mt][h] -> wm*32+mt*16+(lane>>2)+h*8)
    float rs[2][2], rq[2][2];
    #pragma unroll
    for (int mt = 0; mt < 2; mt++) {
        rs[mt][0] = rs[mt][1] = rq[mt][0] = rq[mt][1] = 0.0f;
        const int m = m0 + wm * 32 + mt * 16 + (lane >> 2);
        #pragma unroll
        for (int nf = 0; nf < 8; nf++) {
            const int n = n0 + wn * 64 + nf * 8 + (lane & 3) * 2;
            const float v0 = acc[mt][nf][0] + bv[nf].x;
            const float v1 = acc[mt][nf][1] + bv[nf].y;
            const float v2 = acc[mt][nf][2] + bv[nf].x;
            const float v3 = acc[mt][nf][3] + bv[nf].y;
            rs[mt][0] += v0 + v1;  rq[mt][0] += v0 * v0 + v1 * v1;
            rs[mt][1] += v2 + v3;  rq[mt][1] += v2 * v2 + v3 * v3;
            *(__half2*)&C[(size_t)m * N4 + n]       = __floats2half2_rn(v0, v1);
            *(__half2*)&C[(size_t)(m + 8) * N4 + n] = __floats2half2_rn(v2, v3);
        }
    }

    // reduce across the 4 lanes (lane&3) sharing each row (fixed shfl order)
    #pragma unroll
    for (int mt = 0; mt < 2; mt++)
        #pragma unroll
        for (int h = 0; h < 2; h++) {
            #pragma unroll
            for (int off = 1; off < 4; off <<= 1) {
                rs[mt][h] += __shfl_xor_sync(0xffffffffu, rs[mt][h], off);
                rq[mt][h] += __shfl_xor_sync(0xffffffffu, rq[mt][h], off);
            }
        }

    // stage per-warp row partials: S[wn][128 rows][2]
    float* S = (float*)smem;
    if ((lane & 3) == 0) {
        #pragma unroll
        for (int mt = 0; mt < 2; mt++)
            #pragma unroll
            for (int h = 0; h < 2; h++) {
                const int rl = wm * 32 + mt * 16 + (lane >> 2) + h * 8;
                S[(wn * 128 + rl) * 2 + 0] = rs[mt][h];
                S[(wn * 128 + rl) * 2 + 1] = rq[mt][h];
            }
    }
    __syncthreads();

    // combine the 4 wn slices in fixed order; one thread per row
    if (tid < 128) {
        float s = 0.0f, q = 0.0f;
        #pragma unroll
        for (int w = 0; w < 4; w++) {
            s += S[(w * 128 + tid) * 2 + 0];
            q += S[(w * 128 + tid) * 2 + 1];
        }
        g_part[gemm][blockIdx.x][m0 + tid] = make_float2(s, q);
    }
}

// ---------------------------------------------------------------------------
// Fused LayerNorm + LSTM gates v3: stats from GEMM-epilogue partials
// (single gate sweep). fp16 gate inputs, MUFU-approx transcendentals.
// ---------------------------------------------------------------------------
__device__ __forceinline__ float4 block_reduce_sum4(float4 v)
{
    __shared__ float4 sbuf[8];
    const int lane = threadIdx.x & 31;
    const int warp = threadIdx.x >> 5;
    #pragma unroll
    for (int o = 16; o > 0; o >>= 1) {
        v.x += __shfl_down_sync(0xffffffffu, v.x, o);
        v.y += __shfl_down_sync(0xffffffffu, v.y, o);
        v.z += __shfl_down_sync(0xffffffffu, v.z, o);
        v.w += __shfl_down_sync(0xffffffffu, v.w, o);
    }
    if (lane == 0) sbuf[warp] = v;
    __syncthreads();
    if (warp == 0) {
        v = (lane < 8) ? sbuf[lane] : make_float4(0.f, 0.f, 0.f, 0.f);
        #pragma unroll
        for (int o = 4; o > 0; o >>= 1) {
            v.x += __shfl_down_sync(0xffffffffu, v.x, o);
            v.y += __shfl_down_sync(0xffffffffu, v.y, o);
            v.z += __shfl_down_sync(0xffffffffu, v.z, o);
            v.w += __shfl_down_sync(0xffffffffu, v.w, o);
        }
        if (lane == 0) sbuf[0] = v;
    }
    __syncthreads();
    float4 res = sbuf[0];
    __syncthreads();
    return res;
}

__global__ void __launch_bounds__(256) ln_lstm_kernel(
    const float* __restrict__ c_prev,
    const float* __restrict__ g_i2h,  const float* __restrict__ be_i2h,
    const float* __restrict__ g_h2h,  const float* __restrict__ be_h2h,
    const float* __restrict__ g_c,    const float* __restrict__ be_c,
    float* __restrict__ out_h, float* __restrict__ out_c)
{
    const int row = blockIdx.x;
    const int t   = threadIdx.x;
    const int lane = t & 31;
    const __half2* gi = (const __half2*)g_gi + (size_t)row * (N4 / 2);
    const __half2* gh = (const __half2*)g_gh + (size_t)row * (N4 / 2);

    // Stats from GEMM partials: warp 0 reduces 16 partials per plane.
    __shared__ float sstat[4];    // sum_i, sumsq_i, sum_h, sumsq_h
    if (t < 32) {
        float2 p = (lane < 16) ? g_part[0][lane][row] : g_part[1][lane - 16][row];
        #pragma unroll
        for (int off = 8; off > 0; off >>= 1) {
            p.x += __shfl_down_sync(0xffffffffu, p.x, off, 16);
            p.y += __shfl_down_sync(0xffffffffu, p.y, off, 16);
        }
        if (lane == 0)  { sstat[0] = p.x; sstat[1] = p.y; }
        if (lane == 16) { sstat[2] = p.x; sstat[3] = p.y; }
    }
    __syncthreads();

    const float n1  = (float)N4;
    const float mi  = sstat[0] / n1;
    const float mh  = sstat[2] / n1;
    const float var_i = (sstat[1] - n1 * mi * mi) * (1.0f / (n1 - 1.0f));
    const float var_h = (sstat[3] - n1 * mh * mh) * (1.0f / (n1 - 1.0f));
    const float inv_i = fast_rcp(fast_sqrt(fmaxf(var_i, 0.f)) + 1e-6f);
    const float inv_h = fast_rcp(fast_sqrt(fmaxf(var_h, 0.f)) + 1e-6f);

    // Single gate sweep: normalized gate sums + cell update
    float cn[2][2], og[2][2];
    float4 cs = make_float4(0.f, 0.f, 0.f, 0.f);
    #pragma unroll
    for (int kk = 0; kk < 2; kk++) {
        float sg[4][2];
        #pragma unroll
        for (int g = 0; g < 4; g++) {
            const int h = (g * 2 + kk) * 256 + t;
            const float2 a = __half22float2(gi[h]);
            const float2 b = __half22float2(gh[h]);
            const int pidx = g * 1024 + ((kk * 256 + t) << 1);
            const float2 ga = *(const float2*)(g_i2h + pidx);
            const float2 ba = *(const float2*)(be_i2h + pidx);
            const float2 gb = *(const float2*)(g_h2h + pidx);
            const float2 bb = *(const float2*)(be_h2h + pidx);
            sg[g][0] = ga.x * (a.x - mi) * inv_i + ba.x + gb.x * (b.x - mh) * inv_h + bb.x;
            sg[g][1] = ga.y * (a.y - mi) * inv_i + ba.y + gb.y * (b.y - mh) * inv_h + bb.y;
        }
        const int j = ((kk * 256 + t) << 1);
        const float2 cp = *(const float2*)(c_prev + (size_t)row * HDIM + j);
        const float cpv[2] = {cp.x, cp.y};
        #pragma unroll
        for (int x = 0; x < 2; x++) {
            cn[kk][x] = cpv[x] * fast_sigmoid(sg[1][x] + 1.0f)
                      + fast_tanh(sg[2][x]) * fast_sigmoid(sg[0][x]);
            og[kk][x] = sg[3][x];
            cs.x += cn[kk][x];
            cs.y += cn[kk][x] * cn[kk][x];
        }
    }
    cs = block_reduce_sum4(cs);

    const float n2   = (float)HDIM;
    const float mc   = cs.x / n2;
    const float var_c = (cs.y - n2 * mc * mc) * (1.0f / (n2 - 1.0f));
    const float inv_c = fast_rcp(fast_sqrt(fmaxf(var_c, 0.f)) + 1e-6f);

    #pragma unroll
    for (int kk = 0; kk < 2; kk++) {
        const int j = ((kk * 256 + t) << 1);
        const float2 gcv  = *(const float2*)(g_c + j);
        const float2 becv = *(const float2*)(be_c + j);
        float2 oc, oh;
        oc.x = gcv.x * (cn[kk][0] - mc) * inv_c + becv.x;
        oc.y = gcv.y * (cn[kk][1] - mc) * inv_c + becv.y;
        oh.x = fast_sigmoid(og[kk][0]) * fast_tanh(oc.x);
        oh.y = fast_sigmoid(og[kk][1]) * fast_tanh(oc.y);
        *(float2*)(out_c + (size_t)row * HDIM + j) = oc;
        *(float2*)(out_h + (size_t)row * HDIM + j) = oh;
    }
}

// ---------------------------------------------------------------------------
extern "C" void kernel_launch(void* const* d_in, const int* in_sizes, int n_in,
                              void* d_out, int out_size)
{
    const float* input  = (const float*)d_in[0];
    const float* h_prev = (const float*)d_in[1];
    const float* c_prev = (const float*)d_in[2];
    const float* w_i2h  = (const float*)d_in[3];
    const float* b_i2h  = (const float*)d_in[4];
    const float* w_h2h  = (const float*)d_in[5];
    const float* b_h2h  = (const float*)d_in[6];
    const float* gi2h   = (const float*)d_in[7];
    const float* bei2h  = (const float*)d_in[8];
    const float* gh2h   = (const float*)d_in[9];
    const float* beh2h  = (const float*)d_in[10];
    const float* gc     = (const float*)d_in[11];
    const float* bec    = (const float*)d_in[12];

    float* out_h = (float*)d_out;
    float* out_c = (float*)d_out + (size_t)BSZ * HDIM;

    // conversions
    cast_act_kernel<<<dim3(BSZ * KDIM / (256 * 4), 1, 2), 256>>>(input, h_prev);
    cast_wt_kernel<<<dim3(N4 / 32, KDIM / 32, 2), 128>>>(w_i2h, w_h2h);

    // GEMMs on tensor pipe (mma.sync fp16) + fused row-stat partials
    cudaFuncSetAttribute(gemm_mma_kernel,
                         cudaFuncAttributeMaxDynamicSharedMemorySize, GEMM_SMEM);
    gemm_mma_kernel<<<dim3(N4 / BN, BSZ / BM, 2), 512, GEMM_SMEM>>>(b_i2h, b_h2h);

    ln_lstm_kernel<<<BSZ, 256>>>(c_prev, gi2h, bei2h, gh2h, beh2h, gc, bec,
                                 out_h, out_c);
}

// round 15
// speedup vs baseline: 1.0517x; 1.0517x over previous
#include <cuda_runtime.h>
#include <cuda_fp16.h>
#include <math.h>
#include <stdint.h>

// Problem dims (fixed)
#define BSZ   4096
#define KDIM  1024
#define N4    4096   // 4*H
#define HDIM  1024

// ---------------------------------------------------------------------------
// Device scratch (static, no dynamic allocation)
// ---------------------------------------------------------------------------
__device__ __half g_gi[(size_t)BSZ * N4];   // input  @ w_i2h + b_i2h (fp16)
__device__ __half g_gh[(size_t)BSZ * N4];   // h_prev @ w_h2h + b_h2h (fp16)

// fp16 operands: A [BSZ, KDIM], W transposed [N4, KDIM]
__device__ __half g_a2[2][(size_t)BSZ * KDIM];
__device__ __half g_w2[2][(size_t)N4 * KDIM];

// ---------------------------------------------------------------------------
// Base-PTX helpers (legal on compute_103 virtual arch)
// ---------------------------------------------------------------------------
__device__ __forceinline__ uint32_t smem_u32(const void* p) {
    uint32_t a;
    asm("{ .reg .u64 t; cvta.to.shared.u64 t, %1; cvt.u32.u64 %0, t; }" : "=r"(a) : "l"(p));
    return a;
}
__device__ __forceinline__ void cp_async16(uint32_t s, const void* g) {
    asm volatile("cp.async.cg.shared.global [%0], [%1], 16;" :: "r"(s), "l"(g));
}
#define CP_COMMIT() asm volatile("cp.async.commit_group;" ::: "memory")
#define CP_WAIT(n)  asm volatile("cp.async.wait_group %0;" :: "n"(n) : "memory")

__device__ __forceinline__ void ldsm4(uint32_t& r0, uint32_t& r1, uint32_t& r2, uint32_t& r3,
                                      uint32_t addr) {
    asm volatile("ldmatrix.sync.aligned.m8n8.x4.shared.b16 {%0,%1,%2,%3}, [%4];"
                 : "=r"(r0), "=r"(r1), "=r"(r2), "=r"(r3) : "r"(addr));
}
__device__ __forceinline__ void mma_f16(float* c, const uint32_t* a, const uint32_t* b) {
    asm volatile(
        "mma.sync.aligned.m16n8k16.row.col.f32.f16.f16.f32 "
        "{%0,%1,%2,%3}, {%4,%5,%6,%7}, {%8,%9}, {%0,%1,%2,%3};"
        : "+f"(c[0]), "+f"(c[1]), "+f"(c[2]), "+f"(c[3])
        : "r"(a[0]), "r"(a[1]), "r"(a[2]), "r"(a[3]), "r"(b[0]), "r"(b[1]));
}

// fast transcendental approximations (single MUFU op each)
__device__ __forceinline__ float fast_tanh(float x) {
    float y;
    asm("tanh.approx.f32 %0, %1;" : "=f"(y) : "f"(x));
    return y;
}
__device__ __forceinline__ float fast_sigmoid(float x) {
    float e;
    asm("ex2.approx.f32 %0, %1;" : "=f"(e) : "f"(-1.4426950408889634f * x));
    float r;
    asm("rcp.approx.f32 %0, %1;" : "=f"(r) : "f"(1.0f + e));
    return r;
}
__device__ __forceinline__ float fast_sqrt(float x) {
    float y;
    asm("sqrt.approx.f32 %0, %1;" : "=f"(y) : "f"(x));
    return y;
}
__device__ __forceinline__ float fast_rcp(float x) {
    float y;
    asm("rcp.approx.f32 %0, %1;" : "=f"(y) : "f"(x));
    return y;
}

// ---------------------------------------------------------------------------
// Conversion kernels
// ---------------------------------------------------------------------------
__global__ void __launch_bounds__(256) cast_act_kernel(
    const float* __restrict__ src0, const float* __restrict__ src1)
{
    const int plane = blockIdx.z;
    const float* __restrict__ src = plane ? src1 : src0;
    __half* __restrict__ dst = g_a2[plane];

    const size_t idx = ((size_t)blockIdx.x * 256 + threadIdx.x) * 4;
    float4 v = *(const float4*)(src + idx);
    union { __half2 h2v[2]; uint2 u; } p;
    p.h2v[0] = __floats2half2_rn(v.x, v.y);
    p.h2v[1] = __floats2half2_rn(v.z, v.w);
    *(uint2*)(dst + idx) = p.u;
}

// Weights: W [KDIM, N4] fp32 -> W2 [N4, KDIM] fp16 (transpose), vectorized.
__global__ void __launch_bounds__(128) cast_wt_kernel(
    const float* __restrict__ w0, const float* __restrict__ w1)
{
    const int plane = blockIdx.z;
    const float* __restrict__ W = plane ? w1 : w0;
    __half* __restrict__ D = g_w2[plane];

    __shared__ float tileT[32][33];      // [n][k]
    const int tid = threadIdx.x;
    const int n0 = blockIdx.x * 32;      // N tile
    const int k0 = blockIdx.y * 32;      // K tile

    #pragma unroll
    for (int it = 0; it < 2; it++) {
        const int id = tid + it * 128;
        const int k  = id >> 3;              // 0..31
        const int n4 = (id & 7) * 4;         // 0,4,..28
        const float4 v = *(const float4*)(W + (size_t)(k0 + k) * N4 + n0 + n4);
        tileT[n4 + 0][k] = v.x;
        tileT[n4 + 1][k] = v.y;
        tileT[n4 + 2][k] = v.z;
        tileT[n4 + 3][k] = v.w;
    }
    __syncthreads();

    const int n  = tid >> 2;                 // 0..31
    const int kc = (tid & 3) * 8;            // 0,8,16,24
    union { __half2 h[4]; uint4 u; } o;
    #pragma unroll
    for (int i = 0; i < 4; i++)
        o.h[i] = __floats2half2_rn(tileT[n][kc + i * 2], tileT[n][kc + i * 2 + 1]);
    *(uint4*)(D + (size_t)(n0 + n) * KDIM + k0 + kc) = o.u;
}

// ---------------------------------------------------------------------------
// fp16 mma.sync GEMM: C[4096, 4096] = A[4096,1024] @ W[4096,1024]^T + bias
// CTA tile 128x256, BK=32, 512 threads (16 warps, 4x4), warp tile 32x64,
// 4-stage cp.async pipeline (3 in flight). Output stored fp16.  (R10 winner)
// ---------------------------------------------------------------------------
#define BM 128
#define BN 256
#define BK 32
#define STAGES 4
#define A_ST ((BM) * (BK) * 2)                  // 8192 B
#define B_ST ((BN) * (BK) * 2)                  // 16384 B
#define STAGE_BYTES (A_ST + B_ST)               // 24576 B
#define GEMM_SMEM (STAGES * STAGE_BYTES)        // 98304 B
#define ITERS (KDIM / BK)                       // 32

__device__ __forceinline__ uint32_t sw_off(int r, int chunk) {
    return (uint32_t)(r * 64 + ((chunk ^ ((r >> 1) & 3)) << 4));
}

__device__ __forceinline__ void load_stage(
    uint32_t sA, uint32_t sB,
    const __half* __restrict__ Ag, const __half* __restrict__ Wg,
    int m0, int n0, int kt, int tid)
{
    const int kbase = kt * BK;
    {
        const int r = tid >> 2, kc = tid & 3;
        cp_async16(sA + sw_off(r, kc), Ag + (size_t)(m0 + r) * KDIM + kbase + kc * 8);
    }
    #pragma unroll
    for (int i = 0; i < 2; i++) {
        const int id = tid + i * 512;
        const int r = id >> 2, kc = id & 3;
        cp_async16(sB + sw_off(r, kc), Wg + (size_t)(n0 + r) * KDIM + kbase + kc * 8);
    }
}

__global__ void __launch_bounds__(512, 1) gemm_mma_kernel(
    const float* __restrict__ bias0, const float* __restrict__ bias1)
{
    extern __shared__ char smem[];
    const uint32_t sbase = smem_u32(smem);
    const int tid  = threadIdx.x;
    const int lane = tid & 31;
    const int wid  = tid >> 5;
    const int wm   = wid >> 2;     // 0..3
    const int wn   = wid & 3;      // 0..3

    const int gemm = blockIdx.z;
    const int m0 = blockIdx.y * BM;
    const int n0 = blockIdx.x * BN;

    const __half* __restrict__ Ag = g_a2[gemm];
    const __half* __restrict__ Wg = g_w2[gemm];
    __half* __restrict__ C = gemm ? g_gh : g_gi;
    const float* __restrict__ bias = gemm ? bias1 : bias0;

    float acc[2][8][4];
    #pragma unroll
    for (int i = 0; i < 2; i++)
        #pragma unroll
        for (int j = 0; j < 8; j++)
            #pragma unroll
            for (int r = 0; r < 4; r++)
                acc[i][j][r] = 0.0f;

    const int row_a  = lane & 15;
    const int ksel_a = lane >> 4;
    const int row_b  = ((lane >> 4) << 3) | (lane & 7);
    const int ksel_b = (lane >> 3) & 1;

    load_stage(sbase,                   sbase + A_ST,                   Ag, Wg, m0, n0, 0, tid);
    CP_COMMIT();
    load_stage(sbase + STAGE_BYTES,     sbase + STAGE_BYTES + A_ST,     Ag, Wg, m0, n0, 1, tid);
    CP_COMMIT();
    load_stage(sbase + 2 * STAGE_BYTES, sbase + 2 * STAGE_BYTES + A_ST, Ag, Wg, m0, n0, 2, tid);
    CP_COMMIT();

    #pragma unroll 1
    for (int kt = 0; kt < ITERS; kt++) {
        CP_WAIT(2);
        __syncthreads();
        const int s = kt & 3;
        const uint32_t sA = sbase + s * STAGE_BYTES;
        const uint32_t sB = sA + A_ST;

        #pragma unroll
        for (int ks = 0; ks < 2; ks++) {
            uint32_t a[2][4], b[4][4];
            #pragma unroll
            for (int mt = 0; mt < 2; mt++) {
                const int r = wm * 32 + mt * 16 + row_a;
                ldsm4(a[mt][0], a[mt][1], a[mt][2], a[mt][3],
                      sA + sw_off(r, ks * 2 + ksel_a));
            }
            #pragma unroll
            for (int bt = 0; bt < 4; bt++) {
                const int n = wn * 64 + bt * 16 + row_b;
                ldsm4(b[bt][0], b[bt][1], b[bt][2], b[bt][3],
                      sB + sw_off(n, ks * 2 + ksel_b));
            }
            #pragma unroll
            for (int mt = 0; mt < 2; mt++)
                #pragma unroll
                for (int bt = 0; bt < 4; bt++) {
                    mma_f16(acc[mt][bt * 2],     a[mt], &b[bt][0]);
                    mma_f16(acc[mt][bt * 2 + 1], a[mt], &b[bt][2]);
                }
        }

        if (kt + 3 < ITERS) {
            const int sn = (kt + 3) & 3;
            load_stage(sbase + sn * STAGE_BYTES, sbase + sn * STAGE_BYTES + A_ST,
                       Ag, Wg, m0, n0, kt + 3, tid);
        }
        CP_COMMIT();
    }

    float2 bv[8];
    #pragma unroll
    for (int nf = 0; nf < 8; nf++) {
        const int n = n0 + wn * 64 + nf * 8 + (lane & 3) * 2;
        bv[nf] = *(const float2*)(bias + n);
    }
    #pragma unroll
    for (int mt = 0; mt < 2; mt++) {
        const int m = m0 + wm * 32 + mt * 16 + (lane >> 2);
        #pragma unroll
        for (int nf = 0; nf < 8; nf++) {
            const int n = n0 + wn * 64 + nf * 8 + (lane & 3) * 2;
            const __half2 o0 = __floats2half2_rn(acc[mt][nf][0] + bv[nf].x,
                                                 acc[mt][nf][1] + bv[nf].y);
            const __half2 o1 = __floats2half2_rn(acc[mt][nf][2] + bv[nf].x,
                                                 acc[mt][nf][3] + bv[nf].y);
            *(__half2*)&C[(size_t)m * N4 + n]       = o0;
            *(__half2*)&C[(size_t)(m + 8) * N4 + n] = o1;
        }
    }
}

// ---------------------------------------------------------------------------
// Fused LayerNorm + LSTM gates v4: single pass, column-block ownership.
// Thread t owns columns [4t, 4t+4) of EVERY gate -> gate loads are 8x LDG.64
// (uint2, kept packed in regs), params/c_prev/outputs are 128-bit accesses.
// ---------------------------------------------------------------------------
__device__ __forceinline__ float4 block_reduce_sum4(float4 v)
{
    __shared__ float4 sbuf[8];
    const int lane = threadIdx.x & 31;
    const int warp = threadIdx.x >> 5;
    #pragma unroll
    for (int o = 16; o > 0; o >>= 1) {
        v.x += __shfl_down_sync(0xffffffffu, v.x, o);
        v.y += __shfl_down_sync(0xffffffffu, v.y, o);
        v.z += __shfl_down_sync(0xffffffffu, v.z, o);
        v.w += __shfl_down_sync(0xffffffffu, v.w, o);
    }
    if (lane == 0) sbuf[warp] = v;
    __syncthreads();
    if (warp == 0) {
        v = (lane < 8) ? sbuf[lane] : make_float4(0.f, 0.f, 0.f, 0.f);
        #pragma unroll
        for (int o = 4; o > 0; o >>= 1) {
            v.x += __shfl_down_sync(0xffffffffu, v.x, o);
            v.y += __shfl_down_sync(0xffffffffu, v.y, o);
            v.z += __shfl_down_sync(0xffffffffu, v.z, o);
            v.w += __shfl_down_sync(0xffffffffu, v.w, o);
        }
        if (lane == 0) sbuf[0] = v;
    }
    __syncthreads();
    float4 res = sbuf[0];
    __syncthreads();
    return res;
}

__global__ void __launch_bounds__(256) ln_lstm_kernel(
    const float* __restrict__ c_prev,
    const float* __restrict__ g_i2h,  const float* __restrict__ be_i2h,
    const float* __restrict__ g_h2h,  const float* __restrict__ be_h2h,
    const float* __restrict__ g_c,    const float* __restrict__ be_c,
    float* __restrict__ out_h, float* __restrict__ out_c)
{
    const int row = blockIdx.x;
    const int t   = threadIdx.x;
    const int c4  = t * 4;                    // column base within each gate
    const __half* gi = g_gi + (size_t)row * N4;
    const __half* gh = g_gh + (size_t)row * N4;

    // Load 4 halfs per gate per matrix (8x LDG.64), keep packed.
    union U2 { __half2 h[2]; uint2 u; };
    U2 ai[4], ah[4];
    float4 s = make_float4(0.f, 0.f, 0.f, 0.f);
    #pragma unroll
    for (int g = 0; g < 4; g++) {
        ai[g].u = *(const uint2*)(gi + g * 1024 + c4);
        ah[g].u = *(const uint2*)(gh + g * 1024 + c4);
        const float2 a0 = __half22float2(ai[g].h[0]);
        const float2 a1 = __half22float2(ai[g].h[1]);
        const float2 b0 = __half22float2(ah[g].h[0]);
        const float2 b1 = __half22float2(ah[g].h[1]);
        s.x += (a0.x + a0.y) + (a1.x + a1.y);
        s.y += (a0.x * a0.x + a0.y * a0.y) + (a1.x * a1.x + a1.y * a1.y);
        s.z += (b0.x + b0.y) + (b1.x + b1.y);
        s.w += (b0.x * b0.x + b0.y * b0.y) + (b1.x * b1.x + b1.y * b1.y);
    }
    s = block_reduce_sum4(s);

    const float n1  = (float)N4;
    const float mi  = s.x / n1;
    const float mh  = s.z / n1;
    const float var_i = (s.y - n1 * mi * mi) * (1.0f / (n1 - 1.0f));
    const float var_h = (s.w - n1 * mh * mh) * (1.0f / (n1 - 1.0f));
    const float inv_i = fast_rcp(fast_sqrt(fmaxf(var_i, 0.f)) + 1e-6f);
    const float inv_h = fast_rcp(fast_sqrt(fmaxf(var_h, 0.f)) + 1e-6f);

    // Normalized gate sums for the 4 owned columns of each gate.
    float sg[4][4];
    #pragma unroll
    for (int g = 0; g < 4; g++) {
        const int pidx = g * 1024 + c4;
        const float4 ga = *(const float4*)(g_i2h + pidx);
        const float4 ba = *(const float4*)(be_i2h + pidx);
        const float4 gb = *(const float4*)(g_h2h + pidx);
        const float4 bb = *(const float4*)(be_h2h + pidx);
        const float2 a0 = __half22float2(ai[g].h[0]);
        const float2 a1 = __half22float2(ai[g].h[1]);
        const float2 b0 = __half22float2(ah[g].h[0]);
        const float2 b1 = __half22float2(ah[g].h[1]);
        sg[g][0] = ga.x * (a0.x - mi) * inv_i + ba.x + gb.x * (b0.x - mh) * inv_h + bb.x;
        sg[g][1] = ga.y * (a0.y - mi) * inv_i + ba.y + gb.y * (b0.y - mh) * inv_h + bb.y;
        sg[g][2] = ga.z * (a1.x - mi) * inv_i + ba.z + gb.z * (b1.x - mh) * inv_h + bb.z;
        sg[g][3] = ga.w * (a1.y - mi) * inv_i + ba.w + gb.w * (b1.y - mh) * inv_h + bb.w;
    }

    // gates: i=sg[0], f=sg[1], u=sg[2], o=sg[3]
    const float4 cp = *(const float4*)(c_prev + (size_t)row * HDIM + c4);
    const float cpv[4] = {cp.x, cp.y, cp.z, cp.w};
    float cn[4];
    float4 cs = make_float4(0.f, 0.f, 0.f, 0.f);
    #pragma unroll
    for (int x = 0; x < 4; x++) {
        cn[x] = cpv[x] * fast_sigmoid(sg[1][x] + 1.0f)
              + fast_tanh(sg[2][x]) * fast_sigmoid(sg[0][x]);
        cs.x += cn[x];
        cs.y += cn[x] * cn[x];
    }
    cs = block_reduce_sum4(cs);

    const float n2   = (float)HDIM;
    const float mc   = cs.x / n2;
    const float var_c = (cs.y - n2 * mc * mc) * (1.0f / (n2 - 1.0f));
    const float inv_c = fast_rcp(fast_sqrt(fmaxf(var_c, 0.f)) + 1e-6f);

    const float4 gcv  = *(const float4*)(g_c + c4);
    const float4 becv = *(const float4*)(be_c + c4);
    const float gca[4]  = {gcv.x, gcv.y, gcv.z, gcv.w};
    const float beca[4] = {becv.x, becv.y, becv.z, becv.w};

    float4 oc, oh;
    float* ocp = &oc.x;
    float* ohp = &oh.x;
    #pragma unroll
    for (int x = 0; x < 4; x++) {
        const float cval = gca[x] * (cn[x] - mc) * inv_c + beca[x];
        ocp[x] = cval;
        ohp[x] = fast_sigmoid(sg[3][x]) * fast_tanh(cval);
    }
    *(float4*)(out_c + (size_t)row * HDIM + c4) = oc;
    *(float4*)(out_h + (size_t)row * HDIM + c4) = oh;
}

// ---------------------------------------------------------------------------
extern "C" void kernel_launch(void* const* d_in, const int* in_sizes, int n_in,
                              void* d_out, int out_size)
{
    const float* input  = (const float*)d_in[0];
    const float* h_prev = (const float*)d_in[1];
    const float* c_prev = (const float*)d_in[2];
    const float* w_i2h  = (const float*)d_in[3];
    const float* b_i2h  = (const float*)d_in[4];
    const float* w_h2h  = (const float*)d_in[5];
    const float* b_h2h  = (const float*)d_in[6];
    const float* gi2h   = (const float*)d_in[7];
    const float* bei2h  = (const float*)d_in[8];
    const float* gh2h   = (const float*)d_in[9];
    const float* beh2h  = (const float*)d_in[10];
    const float* gc     = (const float*)d_in[11];
    const float* bec    = (const float*)d_in[12];

    float* out_h = (float*)d_out;
    float* out_c = (float*)d_out + (size_t)BSZ * HDIM;

    // conversions
    cast_act_kernel<<<dim3(BSZ * KDIM / (256 * 4), 1, 2), 256>>>(input, h_prev);
    cast_wt_kernel<<<dim3(N4 / 32, KDIM / 32, 2), 128>>>(w_i2h, w_h2h);

    // GEMMs on tensor pipe (mma.sync fp16, K=1024, 512 threads, 4 stages)
    cudaFuncSetAttribute(gemm_mma_kernel,
                         cudaFuncAttributeMaxDynamicSharedMemorySize, GEMM_SMEM);
    gemm_mma_kernel<<<dim3(N4 / BN, BSZ / BM, 2), 512, GEMM_SMEM>>>(b_i2h, b_h2h);

    ln_lstm_kernel<<<BSZ, 256>>>(c_prev, gi2h, bei2h, gh2h, beh2h, gc, bec,
                                 out_h, out_c);
}